// round 6
// baseline (speedup 1.0000x reference)
#include <cuda_runtime.h>
#include <cstdint>

#define N_NODES 50000
#define N_FEAT  128
#define N_HID   64
#define N_EDGES 800000
#define LRELU   0.05f

// Scratch (static device globals; no allocation allowed)
__device__ float g_out[N_NODES * N_HID];  // output accumulator [N, 64]
__device__ float g_ht[N_NODES * N_HID];   // h_transformed  [N, 64]
__device__ float g_e1[N_NODES];           // h_t[i] . a_w[:64]
__device__ float g_e2[N_NODES];           // h_t[i] . a_w[64:]
__device__ float g_hsum[N_NODES];         // segment sum of exp scores
__device__ float g_hexp[N_EDGES];         // per-edge exp(leakyrelu(z))
__device__ int   g_idx64;                 // 1 if edge_index is int64, 0 if int32

// ---------------------------------------------------------------------------
// Index accessor: row 0 = src, row 1 = dst, layout [2, E] of either dtype.
// Clamped so a wrong dtype guess produces wrong values (rel_err diagnostic),
// never a wild-address trap.
// ---------------------------------------------------------------------------
__device__ __forceinline__ int load_idx(const void* ei, int row, int e)
{
    long long v;
    if (g_idx64) {
        v = ((const long long*)ei)[(long long)row * N_EDGES + e];
    } else {
        v = ((const int*)ei)[(long long)row * N_EDGES + e];
    }
    if (v < 0) v = 0;
    if (v >= N_NODES) v = N_NODES - 1;
    return (int)v;
}

// ---------------------------------------------------------------------------
// Kernel D: detect index dtype. int32 pairs read as int64 give a + b*2^32,
// out of [0, N_NODES) whenever b != 0 — certain over 256 samples.
// ---------------------------------------------------------------------------
__global__ void k_detect(const void* ei)
{
    if (threadIdx.x == 0 && blockIdx.x == 0) {
        const long long* p = (const long long*)ei;
        int is64 = 1;
        for (int i = 0; i < 256; i++) {
            long long v = p[i];
            if (v < 0 || v >= N_NODES) { is64 = 0; break; }
        }
        g_idx64 = is64;
    }
}

// ---------------------------------------------------------------------------
// Kernel 0: zero accumulators (device scratch only)
// ---------------------------------------------------------------------------
__global__ void k_zero()
{
    int i = blockIdx.x * blockDim.x + threadIdx.x;
    if (i < N_NODES * N_HID) g_out[i] = 0.0f;
    if (i < N_NODES)         g_hsum[i] = 0.0f;
}

// ---------------------------------------------------------------------------
// Kernel 1: h_t = x @ W_fc, fused epilogue computes e1, e2 per node.
// ---------------------------------------------------------------------------
__global__ void k_gemm(const float* __restrict__ x,
                       const float* __restrict__ W,
                       const float* __restrict__ aw)
{
    __shared__ float Ws[N_FEAT * N_HID];   // 32 KB
    __shared__ float xs[4 * N_FEAT];       // 2 KB
    __shared__ float p1s[4][2], p2s[4][2];

    const int tid = threadIdx.x;
    const int r   = tid >> 6;      // 0..3  row within group
    const int col = tid & 63;      // 0..63 output column

    for (int i = tid; i < N_FEAT * N_HID; i += 256) Ws[i] = W[i];
    const float a1 = aw[col];
    const float a2 = aw[N_HID + col];
    __syncthreads();

    for (int row0 = blockIdx.x * 4; row0 < N_NODES; row0 += gridDim.x * 4) {
        for (int i = tid; i < 4 * N_FEAT; i += 256)
            xs[i] = x[row0 * N_FEAT + i];
        __syncthreads();

        const float* xr = &xs[r * N_FEAT];
        float acc = 0.0f;
        #pragma unroll
        for (int k = 0; k < N_FEAT; k++)
            acc = fmaf(xr[k], Ws[k * N_HID + col], acc);

        g_ht[(row0 + r) * N_HID + col] = acc;

        float p1 = acc * a1;
        float p2 = acc * a2;
        #pragma unroll
        for (int o = 16; o > 0; o >>= 1) {
            p1 += __shfl_down_sync(0xFFFFFFFFu, p1, o);
            p2 += __shfl_down_sync(0xFFFFFFFFu, p2, o);
        }
        if ((col & 31) == 0) {
            p1s[r][col >> 5] = p1;
            p2s[r][col >> 5] = p2;
        }
        __syncthreads();
        if (col == 0) {
            g_e1[row0 + r] = p1s[r][0] + p1s[r][1];
            g_e2[row0 + r] = p2s[r][0] + p2s[r][1];
        }
        __syncthreads();
    }
}

// ---------------------------------------------------------------------------
// Kernel 2: per-edge score + exp + segment-sum into g_hsum
// ---------------------------------------------------------------------------
__global__ void k_edge_score(const void* __restrict__ ei,
                             const float* __restrict__ ab)
{
    int e = blockIdx.x * blockDim.x + threadIdx.x;
    if (e >= N_EDGES) return;
    int s = load_idx(ei, 0, e);
    int d = load_idx(ei, 1, e);
    float z = g_e1[s] + g_e2[d] + ab[0];
    z = (z >= 0.0f) ? z : LRELU * z;
    float h = __expf(z);
    g_hexp[e] = h;
    atomicAdd(&g_hsum[s], h);
}

// ---------------------------------------------------------------------------
// Kernel 3: alpha = h / h_sum[src]; g_out[src*64+c] += alpha * h_t[dst*64+c]
// One thread per (edge, channel). Gather & scatter coalesced 128B lines.
// ---------------------------------------------------------------------------
__global__ void k_scatter2(const void* __restrict__ ei,
                           float* __restrict__ alpha_out)
{
    long long t = (long long)blockIdx.x * blockDim.x + threadIdx.x;
    int e = (int)(t >> 6);       // edge
    int c = (int)(t & 63);       // channel
    if (e >= N_EDGES) return;

    int s = load_idx(ei, 0, e);
    int d = load_idx(ei, 1, e);
    float alpha = g_hexp[e] / g_hsum[s];
    if (c == 0) alpha_out[e] = alpha;

    float v = g_ht[d * N_HID + c];
    atomicAdd(&g_out[s * N_HID + c], alpha * v);
}

// ---------------------------------------------------------------------------
// Kernel 4: copy accumulator to harness output (plain vector stores)
// ---------------------------------------------------------------------------
__global__ void k_copy_out(float* __restrict__ out)
{
    int i = blockIdx.x * blockDim.x + threadIdx.x;
    int n4 = (N_NODES * N_HID) / 4;
    if (i < n4) {
        reinterpret_cast<float4*>(out)[i] =
            reinterpret_cast<const float4*>(g_out)[i];
    }
}

// ---------------------------------------------------------------------------
extern "C" void kernel_launch(void* const* d_in, const int* in_sizes, int n_in,
                              void* d_out, int out_size)
{
    const float* x   = (const float*)d_in[0];
    const void*  ei  = d_in[1];                 // [2, E] int64 OR int32
    const float* Wfc = (const float*)d_in[2];
    const float* aw  = (const float*)d_in[3];
    const float* ab  = (const float*)d_in[4];

    float* out   = (float*)d_out;                   // [N, 64]
    float* alpha = (float*)d_out + N_NODES * N_HID; // [E]

    // D: index dtype probe
    k_detect<<<1, 32>>>(ei);
    // 0: zero accumulators
    {
        int n = N_NODES * N_HID;
        k_zero<<<(n + 255) / 256, 256>>>();
    }
    // 1: GEMM + e1/e2
    k_gemm<<<888, 256>>>(x, Wfc, aw);
    // 2: edge scores + segment sum
    k_edge_score<<<(N_EDGES + 255) / 256, 256>>>(ei, ab);
    // 3: normalize + scatter
    {
        long long total = (long long)N_EDGES * N_HID;
        k_scatter2<<<(unsigned)((total + 255) / 256), 256>>>(ei, alpha);
    }
    // 4: stream result to d_out
    {
        int n4 = (N_NODES * N_HID) / 4;
        k_copy_out<<<(n4 + 255) / 256, 256>>>(out);
    }
}

// round 8
// speedup vs baseline: 1.3145x; 1.3145x over previous
#include <cuda_runtime.h>
#include <cstdint>

#define N_NODES 50000
#define N_FEAT  128
#define N_HID   64
#define N_EDGES 800000
#define LRELU   0.05f
#define CAP     256     // smem edge cache per node (avg degree 16; global fallback)

// Scratch (static device globals; no allocation allowed)
__device__ float g_ht[N_NODES * N_HID];   // h_transformed  [N, 64]
__device__ float g_e1[N_NODES];           // h_t[i] . a_w[:64]
__device__ float g_e2[N_NODES];           // h_t[i] . a_w[64:]
__device__ float g_hexp[N_EDGES];         // per-edge exp(leakyrelu(z))
__device__ int   g_count[N_NODES];        // out-degree histogram (by src)
__device__ int   g_off[N_NODES];          // CSR offsets
__device__ int   g_cursor[N_NODES];       // placement cursors
__device__ int   g_perm[N_EDGES];         // edge id, segment-ordered
__device__ int   g_dstp[N_EDGES];         // dst,     segment-ordered
__device__ float g_hexpp[N_EDGES];        // hexp,    segment-ordered
__device__ int   g_idx64;                 // 1 if edge_index is int64, 0 if int32

// ---------------------------------------------------------------------------
// Index accessor (dtype detected at runtime; clamped for safety)
// ---------------------------------------------------------------------------
__device__ __forceinline__ int load_idx(const void* ei, int row, int e)
{
    long long v;
    if (g_idx64) v = ((const long long*)ei)[(long long)row * N_EDGES + e];
    else         v = ((const int*)ei)[(long long)row * N_EDGES + e];
    if (v < 0) v = 0;
    if (v >= N_NODES) v = N_NODES - 1;
    return (int)v;
}

__global__ void k_detect(const void* ei)
{
    if (threadIdx.x == 0 && blockIdx.x == 0) {
        const long long* p = (const long long*)ei;
        int is64 = 1;
        for (int i = 0; i < 256; i++) {
            long long v = p[i];
            if (v < 0 || v >= N_NODES) { is64 = 0; break; }
        }
        g_idx64 = is64;
    }
}

__global__ void k_zero_counts()
{
    int i = blockIdx.x * blockDim.x + threadIdx.x;
    if (i < N_NODES) g_count[i] = 0;
}

// ---------------------------------------------------------------------------
// Kernel 1: h_t = x @ W_fc with 2x4 register tiling; fused e1/e2 epilogue.
// Block 256 thr: tx 0..15 (4 cols via float4), ty 0..15 (2 rows).
// Tile: 32 rows x 64 cols. Smem: Ws 32KB + xs 16KB = 48KB (static limit).
// ---------------------------------------------------------------------------
__global__ void k_gemm(const float* __restrict__ x,
                       const float* __restrict__ W,
                       const float* __restrict__ aw)
{
    __shared__ float Ws[N_FEAT * N_HID];   // 32 KB  [k][col]
    __shared__ float xs[32 * N_FEAT];      // 16 KB  [row][k]

    const int tid = threadIdx.x;
    const int tx  = tid & 15;        // col group: cols 4tx..4tx+3
    const int ty  = tid >> 4;        // row group: rows 2ty..2ty+1
    const int row0 = blockIdx.x * 32;

    // stage W (k-major [128,64]) via float4: 2048 float4 = 256 thr x 8
    {
        const float4* Wg = (const float4*)W;
        float4* Wsm = (float4*)Ws;
        #pragma unroll
        for (int i = 0; i < 8; i++) Wsm[tid + i * 256] = Wg[tid + i * 256];
    }
    // stage 32 rows of x via float4: 1024 float4 = 256 thr x 4
    {
        float4* xsm = (float4*)xs;
        #pragma unroll
        for (int i = 0; i < 4; i++) {
            int i4 = tid + i * 256;            // float4 index in tile
            int row = row0 + (i4 >> 5);        // 32 float4 per row
            float4 v = make_float4(0.f, 0.f, 0.f, 0.f);
            if (row < N_NODES)
                v = ((const float4*)x)[(long long)row * 32 + (i4 & 31)];
            xsm[i4] = v;
        }
    }
    const float4 a1v = ((const float4*)aw)[tx];
    const float4 a2v = ((const float4*)(aw + N_HID))[tx];
    __syncthreads();

    float acc[2][4];
    #pragma unroll
    for (int i = 0; i < 2; i++)
        #pragma unroll
        for (int j = 0; j < 4; j++) acc[i][j] = 0.0f;

    #pragma unroll 8
    for (int k = 0; k < N_FEAT; k++) {
        float4 w = *(const float4*)&Ws[k * N_HID + tx * 4];
        float x0 = xs[(ty * 2 + 0) * N_FEAT + k];
        float x1 = xs[(ty * 2 + 1) * N_FEAT + k];
        acc[0][0] = fmaf(x0, w.x, acc[0][0]);
        acc[0][1] = fmaf(x0, w.y, acc[0][1]);
        acc[0][2] = fmaf(x0, w.z, acc[0][2]);
        acc[0][3] = fmaf(x0, w.w, acc[0][3]);
        acc[1][0] = fmaf(x1, w.x, acc[1][0]);
        acc[1][1] = fmaf(x1, w.y, acc[1][1]);
        acc[1][2] = fmaf(x1, w.z, acc[1][2]);
        acc[1][3] = fmaf(x1, w.w, acc[1][3]);
    }

    // epilogue: store h_t rows + reduce e1/e2 across the 16 col-groups.
    // Within a warp, lanes = tx + 16*(ty&1): xor over 8..1 reduces across tx.
    #pragma unroll
    for (int i = 0; i < 2; i++) {
        int row = row0 + ty * 2 + i;
        float p1 = acc[i][0] * a1v.x + acc[i][1] * a1v.y +
                   acc[i][2] * a1v.z + acc[i][3] * a1v.w;
        float p2 = acc[i][0] * a2v.x + acc[i][1] * a2v.y +
                   acc[i][2] * a2v.z + acc[i][3] * a2v.w;
        #pragma unroll
        for (int o = 8; o > 0; o >>= 1) {
            p1 += __shfl_xor_sync(0xFFFFFFFFu, p1, o);
            p2 += __shfl_xor_sync(0xFFFFFFFFu, p2, o);
        }
        if (row < N_NODES) {
            *(float4*)&g_ht[(long long)row * N_HID + tx * 4] =
                make_float4(acc[i][0], acc[i][1], acc[i][2], acc[i][3]);
            if (tx == 0) { g_e1[row] = p1; g_e2[row] = p2; }
        }
    }
}

// ---------------------------------------------------------------------------
// Kernel 2: per-edge score + exp, fused src histogram (int atomics)
// ---------------------------------------------------------------------------
__global__ void k_edge_score(const void* __restrict__ ei,
                             const float* __restrict__ ab)
{
    int e = blockIdx.x * blockDim.x + threadIdx.x;
    if (e >= N_EDGES) return;
    int s = load_idx(ei, 0, e);
    int d = load_idx(ei, 1, e);
    float z = g_e1[s] + g_e2[d] + ab[0];
    z = (z >= 0.0f) ? z : LRELU * z;
    g_hexp[e] = __expf(z);
    atomicAdd(&g_count[s], 1);
}

// ---------------------------------------------------------------------------
// Kernel 3: exclusive scan of counts -> offsets (+ cursors). 1 block, 1024 thr.
// ---------------------------------------------------------------------------
__global__ void k_scan()
{
    __shared__ int part[1024];
    const int IT = (N_NODES + 1023) / 1024;   // 49
    int t = threadIdx.x;
    int base = t * IT;

    int s = 0;
    for (int i = 0; i < IT; i++) {
        int idx = base + i;
        if (idx < N_NODES) s += g_count[idx];
    }
    part[t] = s;
    __syncthreads();
    for (int off = 1; off < 1024; off <<= 1) {
        int v = (t >= off) ? part[t - off] : 0;
        __syncthreads();
        part[t] += v;
        __syncthreads();
    }
    int run = (t == 0) ? 0 : part[t - 1];
    for (int i = 0; i < IT; i++) {
        int idx = base + i;
        if (idx < N_NODES) {
            g_off[idx] = run;
            g_cursor[idx] = run;
            run += g_count[idx];
        }
    }
}

// ---------------------------------------------------------------------------
// Kernel 4: place edges into segment order; stash dst & hexp permuted so the
// accumulate pass reads them coalesced.
// ---------------------------------------------------------------------------
__global__ void k_place(const void* __restrict__ ei)
{
    int e = blockIdx.x * blockDim.x + threadIdx.x;
    if (e >= N_EDGES) return;
    int s = load_idx(ei, 0, e);
    int d = load_idx(ei, 1, e);
    float h = g_hexp[e];
    int pos = atomicAdd(&g_cursor[s], 1);
    g_perm[pos]  = e;
    g_dstp[pos]  = d;
    g_hexpp[pos] = h;
}

// ---------------------------------------------------------------------------
// Kernel 5: per-node accumulate. Block = 64 threads = one node.
// Local h_sum (no atomics), register accumulation, one coalesced store.
// ---------------------------------------------------------------------------
__global__ void k_accum(float* __restrict__ out,
                        float* __restrict__ alpha_out)
{
    __shared__ int   pe[CAP];
    __shared__ int   sd[CAP];
    __shared__ float sh[CAP];
    __shared__ float wsum[2];

    int s   = blockIdx.x;
    int c   = threadIdx.x;          // 0..63 channel
    int off = g_off[s];
    int cnt = g_count[s];

    // pass 1: load segment, cache in smem, sum hexp
    float sum = 0.0f;
    for (int j = c; j < cnt; j += 64) {
        int   e  = g_perm[off + j];
        int   d  = g_dstp[off + j];
        float hv = g_hexpp[off + j];
        if (j < CAP) { pe[j] = e; sd[j] = d; sh[j] = hv; }
        sum += hv;
    }
    #pragma unroll
    for (int o = 16; o > 0; o >>= 1)
        sum += __shfl_xor_sync(0xFFFFFFFFu, sum, o);
    if ((c & 31) == 0) wsum[c >> 5] = sum;
    __syncthreads();
    float total = wsum[0] + wsum[1];
    float inv = (cnt > 0) ? (1.0f / total) : 0.0f;

    // pass 2: accumulate alpha * h_t[dst]
    float acc = 0.0f;
    #pragma unroll 4
    for (int j = 0; j < cnt; j++) {
        int   e  = (j < CAP) ? pe[j] : g_perm[off + j];
        int   d  = (j < CAP) ? sd[j] : g_dstp[off + j];
        float hv = (j < CAP) ? sh[j] : g_hexpp[off + j];
        float alpha = hv * inv;
        if (c == (j & 63)) alpha_out[e] = alpha;
        acc = fmaf(alpha, g_ht[(long long)d * N_HID + c], acc);
    }
    out[(long long)s * N_HID + c] = acc;
}

// ---------------------------------------------------------------------------
extern "C" void kernel_launch(void* const* d_in, const int* in_sizes, int n_in,
                              void* d_out, int out_size)
{
    const float* x   = (const float*)d_in[0];
    const void*  ei  = d_in[1];                 // [2, E] int32 or int64
    const float* Wfc = (const float*)d_in[2];
    const float* aw  = (const float*)d_in[3];
    const float* ab  = (const float*)d_in[4];

    float* out   = (float*)d_out;                   // [N, 64]
    float* alpha = (float*)d_out + N_NODES * N_HID; // [E]

    k_detect<<<1, 32>>>(ei);
    k_zero_counts<<<(N_NODES + 255) / 256, 256>>>();
    k_gemm<<<(N_NODES + 31) / 32, 256>>>(x, Wfc, aw);
    k_edge_score<<<(N_EDGES + 255) / 256, 256>>>(ei, ab);
    k_scan<<<1, 1024>>>();
    k_place<<<(N_EDGES + 255) / 256, 256>>>(ei);
    k_accum<<<N_NODES, 64>>>(out, alpha);
}

// round 9
// speedup vs baseline: 2.3658x; 1.7998x over previous
#include <cuda_runtime.h>
#include <cstdint>

#define N_NODES 50000
#define N_FEAT  128
#define N_HID   64
#define N_EDGES 800000
#define LRELU   0.05f
#define CAP     128     // smem edge cache per node (avg degree 16; global fallback)
#define SCAN_BLOCKS ((N_NODES + 255) / 256)   // 196

// Scratch (static device globals; no allocation allowed)
__device__ float g_ht[N_NODES * N_HID];   // h_transformed  [N, 64]
__device__ float g_e1[N_NODES];           // h_t[i] . a_w[:64]
__device__ float g_e2[N_NODES];           // h_t[i] . a_w[64:]
__device__ int   g_count[N_NODES];        // out-degree histogram (by src)
__device__ int   g_off[N_NODES];          // CSR offsets
__device__ int   g_cursor[N_NODES];       // placement cursors
__device__ int   g_bsum[SCAN_BLOCKS];     // per-block count sums
__device__ int   g_boff[SCAN_BLOCKS];     // per-block scan bases
__device__ int   g_perm[N_EDGES];         // edge id, segment-ordered
__device__ int   g_dstp[N_EDGES];         // dst,     segment-ordered
__device__ float g_hexpp[N_EDGES];        // hexp,    segment-ordered
__device__ int   g_idx64;                 // 1 if edge_index is int64, 0 if int32

// ---------------------------------------------------------------------------
__device__ __forceinline__ int load_idx(const void* ei, int row, int e)
{
    long long v;
    if (g_idx64) v = ((const long long*)ei)[(long long)row * N_EDGES + e];
    else         v = ((const int*)ei)[(long long)row * N_EDGES + e];
    if (v < 0) v = 0;
    if (v >= N_NODES) v = N_NODES - 1;
    return (int)v;
}

__global__ void k_detect(const void* ei)
{
    if (threadIdx.x == 0 && blockIdx.x == 0) {
        const long long* p = (const long long*)ei;
        int is64 = 1;
        for (int i = 0; i < 64; i++) {
            long long v = p[i];
            if (v < 0 || v >= N_NODES) { is64 = 0; break; }
        }
        g_idx64 = is64;
    }
}

__global__ void k_zero_counts()
{
    int i = blockIdx.x * blockDim.x + threadIdx.x;
    if (i < N_NODES) g_count[i] = 0;
}

// ---------------------------------------------------------------------------
// Kernel 1: h_t = x @ W_fc with 2x4 register tiling; fused e1/e2 epilogue.
// Tile 32 rows x 64 cols. Smem 48KB (static limit).
// ---------------------------------------------------------------------------
__global__ void k_gemm(const float* __restrict__ x,
                       const float* __restrict__ W,
                       const float* __restrict__ aw)
{
    __shared__ float Ws[N_FEAT * N_HID];   // 32 KB  [k][col]
    __shared__ float xs[32 * N_FEAT];      // 16 KB  [row][k]

    const int tid = threadIdx.x;
    const int tx  = tid & 15;
    const int ty  = tid >> 4;
    const int row0 = blockIdx.x * 32;

    {
        const float4* Wg = (const float4*)W;
        float4* Wsm = (float4*)Ws;
        #pragma unroll
        for (int i = 0; i < 8; i++) Wsm[tid + i * 256] = Wg[tid + i * 256];
    }
    {
        float4* xsm = (float4*)xs;
        #pragma unroll
        for (int i = 0; i < 4; i++) {
            int i4 = tid + i * 256;
            int row = row0 + (i4 >> 5);
            float4 v = make_float4(0.f, 0.f, 0.f, 0.f);
            if (row < N_NODES)
                v = ((const float4*)x)[(long long)row * 32 + (i4 & 31)];
            xsm[i4] = v;
        }
    }
    const float4 a1v = ((const float4*)aw)[tx];
    const float4 a2v = ((const float4*)(aw + N_HID))[tx];
    __syncthreads();

    float acc[2][4];
    #pragma unroll
    for (int i = 0; i < 2; i++)
        #pragma unroll
        for (int j = 0; j < 4; j++) acc[i][j] = 0.0f;

    #pragma unroll 8
    for (int k = 0; k < N_FEAT; k++) {
        float4 w = *(const float4*)&Ws[k * N_HID + tx * 4];
        float x0 = xs[(ty * 2 + 0) * N_FEAT + k];
        float x1 = xs[(ty * 2 + 1) * N_FEAT + k];
        acc[0][0] = fmaf(x0, w.x, acc[0][0]);
        acc[0][1] = fmaf(x0, w.y, acc[0][1]);
        acc[0][2] = fmaf(x0, w.z, acc[0][2]);
        acc[0][3] = fmaf(x0, w.w, acc[0][3]);
        acc[1][0] = fmaf(x1, w.x, acc[1][0]);
        acc[1][1] = fmaf(x1, w.y, acc[1][1]);
        acc[1][2] = fmaf(x1, w.z, acc[1][2]);
        acc[1][3] = fmaf(x1, w.w, acc[1][3]);
    }

    #pragma unroll
    for (int i = 0; i < 2; i++) {
        int row = row0 + ty * 2 + i;
        float p1 = acc[i][0] * a1v.x + acc[i][1] * a1v.y +
                   acc[i][2] * a1v.z + acc[i][3] * a1v.w;
        float p2 = acc[i][0] * a2v.x + acc[i][1] * a2v.y +
                   acc[i][2] * a2v.z + acc[i][3] * a2v.w;
        #pragma unroll
        for (int o = 8; o > 0; o >>= 1) {
            p1 += __shfl_xor_sync(0xFFFFFFFFu, p1, o);
            p2 += __shfl_xor_sync(0xFFFFFFFFu, p2, o);
        }
        if (row < N_NODES) {
            *(float4*)&g_ht[(long long)row * N_HID + tx * 4] =
                make_float4(acc[i][0], acc[i][1], acc[i][2], acc[i][3]);
            if (tx == 0) { g_e1[row] = p1; g_e2[row] = p2; }
        }
    }
}

// ---------------------------------------------------------------------------
// Kernel 2: src out-degree histogram (reads src row only)
// ---------------------------------------------------------------------------
__global__ void k_hist(const void* __restrict__ ei)
{
    int e = blockIdx.x * blockDim.x + threadIdx.x;
    if (e >= N_EDGES) return;
    atomicAdd(&g_count[load_idx(ei, 0, e)], 1);
}

// ---------------------------------------------------------------------------
// Hierarchical exclusive scan: A) block sums  B) scan of sums  C) offsets
// ---------------------------------------------------------------------------
__global__ void k_scanA()
{
    __shared__ int sh[256];
    int idx = blockIdx.x * 256 + threadIdx.x;
    int v = (idx < N_NODES) ? g_count[idx] : 0;
    sh[threadIdx.x] = v;
    __syncthreads();
    for (int o = 128; o > 0; o >>= 1) {
        if (threadIdx.x < o) sh[threadIdx.x] += sh[threadIdx.x + o];
        __syncthreads();
    }
    if (threadIdx.x == 0) g_bsum[blockIdx.x] = sh[0];
}

__global__ void k_scanB()
{
    __shared__ int sh[256];
    int t = threadIdx.x;
    sh[t] = (t < SCAN_BLOCKS) ? g_bsum[t] : 0;
    __syncthreads();
    for (int o = 1; o < 256; o <<= 1) {
        int v = (t >= o) ? sh[t - o] : 0;
        __syncthreads();
        sh[t] += v;
        __syncthreads();
    }
    if (t < SCAN_BLOCKS) g_boff[t] = (t == 0) ? 0 : sh[t - 1];
}

__global__ void k_scanC()
{
    __shared__ int sh[256];
    int t = threadIdx.x;
    int idx = blockIdx.x * 256 + t;
    int v = (idx < N_NODES) ? g_count[idx] : 0;
    sh[t] = v;
    __syncthreads();
    for (int o = 1; o < 256; o <<= 1) {
        int u = (t >= o) ? sh[t - o] : 0;
        __syncthreads();
        sh[t] += u;
        __syncthreads();
    }
    if (idx < N_NODES) {
        int off = g_boff[blockIdx.x] + sh[t] - v;   // exclusive
        g_off[idx] = off;
        g_cursor[idx] = off;
    }
}

// ---------------------------------------------------------------------------
// Kernel 3: fused score + place. Computes exp(leakyrelu(z)) and writes it
// directly into segment order (no unpermuted hexp array).
// ---------------------------------------------------------------------------
__global__ void k_place_score(const void* __restrict__ ei,
                              const float* __restrict__ ab)
{
    int e = blockIdx.x * blockDim.x + threadIdx.x;
    if (e >= N_EDGES) return;
    int s = load_idx(ei, 0, e);
    int d = load_idx(ei, 1, e);
    float z = g_e1[s] + g_e2[d] + ab[0];
    z = (z >= 0.0f) ? z : LRELU * z;
    float h = __expf(z);
    int pos = atomicAdd(&g_cursor[s], 1);
    g_perm[pos]  = e;
    g_dstp[pos]  = d;
    g_hexpp[pos] = h;
}

// ---------------------------------------------------------------------------
// Kernel 4: per-node accumulate, 4 nodes per 256-thread block.
// No float atomics; alpha precomputed to smem; 4-way MLP in gather loop.
// ---------------------------------------------------------------------------
__global__ void k_accum(float* __restrict__ out,
                        float* __restrict__ alpha_out)
{
    __shared__ int   sd[4][CAP];
    __shared__ int   pe[4][CAP];
    __shared__ float sa[4][CAP];
    __shared__ float wsum[4][2];

    const int g = threadIdx.x >> 6;    // node within block (0..3)
    const int c = threadIdx.x & 63;    // channel
    const int s = blockIdx.x * 4 + g;  // 12500*4 = 50000 exact
    const int off = g_off[s];
    const int cnt = g_count[s];

    // pass 1: load segment, cache, sum hexp
    float sum = 0.0f;
    for (int j = c; j < cnt; j += 64) {
        int   d  = g_dstp[off + j];
        float hv = g_hexpp[off + j];
        int   e  = g_perm[off + j];
        if (j < CAP) { sd[g][j] = d; pe[g][j] = e; sa[g][j] = hv; }
        sum += hv;
    }
    #pragma unroll
    for (int o = 16; o > 0; o >>= 1)
        sum += __shfl_xor_sync(0xFFFFFFFFu, sum, o);
    if ((c & 31) == 0) wsum[g][c >> 5] = sum;
    __syncthreads();
    float total = wsum[g][0] + wsum[g][1];
    float inv = (cnt > 0) ? (1.0f / total) : 0.0f;

    // pass 1b: convert cached hexp -> alpha, store alpha_out (parallel over j)
    for (int j = c; j < cnt; j += 64) {
        if (j < CAP) {
            float a = sa[g][j] * inv;
            sa[g][j] = a;
            alpha_out[pe[g][j]] = a;
        } else {
            alpha_out[g_perm[off + j]] = g_hexpp[off + j] * inv;
        }
    }
    __syncthreads();

    // pass 2: acc += alpha * h_t[dst][c], 4 independent chains
    float a0 = 0.f, a1 = 0.f, a2 = 0.f, a3 = 0.f;
    int lim = (cnt < CAP) ? cnt : CAP;
    int j = 0;
    for (; j + 4 <= lim; j += 4) {
        a0 = fmaf(sa[g][j+0], g_ht[(long long)sd[g][j+0] * N_HID + c], a0);
        a1 = fmaf(sa[g][j+1], g_ht[(long long)sd[g][j+1] * N_HID + c], a1);
        a2 = fmaf(sa[g][j+2], g_ht[(long long)sd[g][j+2] * N_HID + c], a2);
        a3 = fmaf(sa[g][j+3], g_ht[(long long)sd[g][j+3] * N_HID + c], a3);
    }
    for (; j < cnt; j++) {
        int   d = (j < CAP) ? sd[g][j] : g_dstp[off + j];
        float a = (j < CAP) ? sa[g][j] : g_hexpp[off + j] * inv;
        a0 = fmaf(a, g_ht[(long long)d * N_HID + c], a0);
    }
    out[(long long)s * N_HID + c] = (a0 + a1) + (a2 + a3);
}

// ---------------------------------------------------------------------------
extern "C" void kernel_launch(void* const* d_in, const int* in_sizes, int n_in,
                              void* d_out, int out_size)
{
    const float* x   = (const float*)d_in[0];
    const void*  ei  = d_in[1];                 // [2, E] int32 or int64
    const float* Wfc = (const float*)d_in[2];
    const float* aw  = (const float*)d_in[3];
    const float* ab  = (const float*)d_in[4];

    float* out   = (float*)d_out;                   // [N, 64]
    float* alpha = (float*)d_out + N_NODES * N_HID; // [E]

    k_detect<<<1, 32>>>(ei);
    k_zero_counts<<<(N_NODES + 255) / 256, 256>>>();
    k_gemm<<<(N_NODES + 31) / 32, 256>>>(x, Wfc, aw);
    k_hist<<<(N_EDGES + 255) / 256, 256>>>(ei);
    k_scanA<<<SCAN_BLOCKS, 256>>>();
    k_scanB<<<1, 256>>>();
    k_scanC<<<SCAN_BLOCKS, 256>>>();
    k_place_score<<<(N_EDGES + 255) / 256, 256>>>(ei, ab);
    k_accum<<<N_NODES / 4, 256>>>(out, alpha);
}

// round 10
// speedup vs baseline: 2.6127x; 1.1044x over previous
#include <cuda_runtime.h>
#include <cstdint>

#define N_NODES 50000
#define N_FEAT  128
#define N_HID   64
#define N_EDGES 800000
#define LRELU   0.05f
#define SCAN_BLOCKS ((N_NODES + 255) / 256)   // 196

// Scratch (static device globals; no allocation allowed)
__device__ float g_ht[N_NODES * N_HID];   // h_transformed  [N, 64]
__device__ float g_e1[N_NODES];           // h_t[i] . a_w[:64]
__device__ float g_e2[N_NODES];           // h_t[i] . a_w[64:]
__device__ float g_hexp[N_EDGES];         // per-edge exp(leakyrelu(z))
__device__ float g_hsum[N_NODES];         // segment sum of hexp by src
__device__ int   g_count[N_NODES];        // out-degree histogram (by src)
__device__ int   g_off[N_NODES];          // CSR offsets
__device__ int   g_cursor[N_NODES];       // placement cursors
__device__ int   g_bsum[SCAN_BLOCKS];     // per-block count sums
__device__ int   g_boff[SCAN_BLOCKS];     // per-block scan bases
__device__ int2  g_ea[N_EDGES];           // packed {dst, alpha-bits}, segment-ordered
__device__ int   g_idx64;                 // 1 if edge_index is int64, 0 if int32

// ---------------------------------------------------------------------------
__device__ __forceinline__ int load_idx(const void* ei, int row, int e)
{
    long long v;
    if (g_idx64) v = ((const long long*)ei)[(long long)row * N_EDGES + e];
    else         v = ((const int*)ei)[(long long)row * N_EDGES + e];
    if (v < 0) v = 0;
    if (v >= N_NODES) v = N_NODES - 1;
    return (int)v;
}

__global__ void k_detect(const void* ei)
{
    if (threadIdx.x == 0 && blockIdx.x == 0) {
        const long long* p = (const long long*)ei;
        int is64 = 1;
        for (int i = 0; i < 64; i++) {
            long long v = p[i];
            if (v < 0 || v >= N_NODES) { is64 = 0; break; }
        }
        g_idx64 = is64;
    }
}

__global__ void k_zero()
{
    int i = blockIdx.x * blockDim.x + threadIdx.x;
    if (i < N_NODES) { g_count[i] = 0; g_hsum[i] = 0.0f; }
}

// ---------------------------------------------------------------------------
// Kernel 1: h_t = x @ W_fc with 2x4 register tiling; fused e1/e2 epilogue.
// Tile 32 rows x 64 cols. Smem 48KB (static limit).
// ---------------------------------------------------------------------------
__global__ void k_gemm(const float* __restrict__ x,
                       const float* __restrict__ W,
                       const float* __restrict__ aw)
{
    __shared__ float Ws[N_FEAT * N_HID];   // 32 KB  [k][col]
    __shared__ float xs[32 * N_FEAT];      // 16 KB  [row][k]

    const int tid = threadIdx.x;
    const int tx  = tid & 15;
    const int ty  = tid >> 4;
    const int row0 = blockIdx.x * 32;

    {
        const float4* Wg = (const float4*)W;
        float4* Wsm = (float4*)Ws;
        #pragma unroll
        for (int i = 0; i < 8; i++) Wsm[tid + i * 256] = Wg[tid + i * 256];
    }
    {
        float4* xsm = (float4*)xs;
        #pragma unroll
        for (int i = 0; i < 4; i++) {
            int i4 = tid + i * 256;
            int row = row0 + (i4 >> 5);
            float4 v = make_float4(0.f, 0.f, 0.f, 0.f);
            if (row < N_NODES)
                v = ((const float4*)x)[(long long)row * 32 + (i4 & 31)];
            xsm[i4] = v;
        }
    }
    const float4 a1v = ((const float4*)aw)[tx];
    const float4 a2v = ((const float4*)(aw + N_HID))[tx];
    __syncthreads();

    float acc[2][4];
    #pragma unroll
    for (int i = 0; i < 2; i++)
        #pragma unroll
        for (int j = 0; j < 4; j++) acc[i][j] = 0.0f;

    #pragma unroll 8
    for (int k = 0; k < N_FEAT; k++) {
        float4 w = *(const float4*)&Ws[k * N_HID + tx * 4];
        float x0 = xs[(ty * 2 + 0) * N_FEAT + k];
        float x1 = xs[(ty * 2 + 1) * N_FEAT + k];
        acc[0][0] = fmaf(x0, w.x, acc[0][0]);
        acc[0][1] = fmaf(x0, w.y, acc[0][1]);
        acc[0][2] = fmaf(x0, w.z, acc[0][2]);
        acc[0][3] = fmaf(x0, w.w, acc[0][3]);
        acc[1][0] = fmaf(x1, w.x, acc[1][0]);
        acc[1][1] = fmaf(x1, w.y, acc[1][1]);
        acc[1][2] = fmaf(x1, w.z, acc[1][2]);
        acc[1][3] = fmaf(x1, w.w, acc[1][3]);
    }

    #pragma unroll
    for (int i = 0; i < 2; i++) {
        int row = row0 + ty * 2 + i;
        float p1 = acc[i][0] * a1v.x + acc[i][1] * a1v.y +
                   acc[i][2] * a1v.z + acc[i][3] * a1v.w;
        float p2 = acc[i][0] * a2v.x + acc[i][1] * a2v.y +
                   acc[i][2] * a2v.z + acc[i][3] * a2v.w;
        #pragma unroll
        for (int o = 8; o > 0; o >>= 1) {
            p1 += __shfl_xor_sync(0xFFFFFFFFu, p1, o);
            p2 += __shfl_xor_sync(0xFFFFFFFFu, p2, o);
        }
        if (row < N_NODES) {
            *(float4*)&g_ht[(long long)row * N_HID + tx * 4] =
                make_float4(acc[i][0], acc[i][1], acc[i][2], acc[i][3]);
            if (tx == 0) { g_e1[row] = p1; g_e2[row] = p2; }
        }
    }
}

// ---------------------------------------------------------------------------
// Kernel 2: fused score + histogram + h_sum. One edge pass.
// ---------------------------------------------------------------------------
__global__ void k_score_hist(const void* __restrict__ ei,
                             const float* __restrict__ ab)
{
    int e = blockIdx.x * blockDim.x + threadIdx.x;
    if (e >= N_EDGES) return;
    int s = load_idx(ei, 0, e);
    int d = load_idx(ei, 1, e);
    float z = g_e1[s] + g_e2[d] + ab[0];
    z = (z >= 0.0f) ? z : LRELU * z;
    float h = __expf(z);
    g_hexp[e] = h;
    atomicAdd(&g_count[s], 1);
    atomicAdd(&g_hsum[s], h);
}

// ---------------------------------------------------------------------------
// Hierarchical exclusive scan: A) block sums  B) scan of sums  C) offsets
// ---------------------------------------------------------------------------
__global__ void k_scanA()
{
    __shared__ int sh[256];
    int idx = blockIdx.x * 256 + threadIdx.x;
    int v = (idx < N_NODES) ? g_count[idx] : 0;
    sh[threadIdx.x] = v;
    __syncthreads();
    for (int o = 128; o > 0; o >>= 1) {
        if (threadIdx.x < o) sh[threadIdx.x] += sh[threadIdx.x + o];
        __syncthreads();
    }
    if (threadIdx.x == 0) g_bsum[blockIdx.x] = sh[0];
}

__global__ void k_scanB()
{
    __shared__ int sh[256];
    int t = threadIdx.x;
    sh[t] = (t < SCAN_BLOCKS) ? g_bsum[t] : 0;
    __syncthreads();
    for (int o = 1; o < 256; o <<= 1) {
        int v = (t >= o) ? sh[t - o] : 0;
        __syncthreads();
        sh[t] += v;
        __syncthreads();
    }
    if (t < SCAN_BLOCKS) g_boff[t] = (t == 0) ? 0 : sh[t - 1];
}

__global__ void k_scanC()
{
    __shared__ int sh[256];
    int t = threadIdx.x;
    int idx = blockIdx.x * 256 + t;
    int v = (idx < N_NODES) ? g_count[idx] : 0;
    sh[t] = v;
    __syncthreads();
    for (int o = 1; o < 256; o <<= 1) {
        int u = (t >= o) ? sh[t - o] : 0;
        __syncthreads();
        sh[t] += u;
        __syncthreads();
    }
    if (idx < N_NODES) {
        int off = g_boff[blockIdx.x] + sh[t] - v;   // exclusive
        g_off[idx] = off;
        g_cursor[idx] = off;
    }
}

// ---------------------------------------------------------------------------
// Kernel 3: place. alpha = hexp/hsum[src] -> alpha_out coalesced; one packed
// 8B {dst, alpha} scattered store into segment order.
// ---------------------------------------------------------------------------
__global__ void k_place(const void* __restrict__ ei,
                        float* __restrict__ alpha_out)
{
    int e = blockIdx.x * blockDim.x + threadIdx.x;
    if (e >= N_EDGES) return;
    int s = load_idx(ei, 0, e);
    int d = load_idx(ei, 1, e);
    float a = g_hexp[e] / g_hsum[s];
    alpha_out[e] = a;
    int pos = atomicAdd(&g_cursor[s], 1);
    g_ea[pos] = make_int2(d, __float_as_int(a));
}

// ---------------------------------------------------------------------------
// Kernel 4: per-node accumulate, 4 nodes per 256-thread block.
// Pure gather: acc += alpha * h_t[dst][c]. No reductions, no scatters.
// ---------------------------------------------------------------------------
__global__ void k_accum(float* __restrict__ out)
{
    const int g = threadIdx.x >> 6;    // node within block (0..3)
    const int c = threadIdx.x & 63;    // channel
    const int s = blockIdx.x * 4 + g;  // 12500*4 = 50000 exact
    const int off = g_off[s];
    const int cnt = g_count[s];

    float a0 = 0.f, a1 = 0.f, a2 = 0.f, a3 = 0.f;
    int j = 0;
    for (; j + 4 <= cnt; j += 4) {
        int2 e0 = g_ea[off + j + 0];
        int2 e1 = g_ea[off + j + 1];
        int2 e2 = g_ea[off + j + 2];
        int2 e3 = g_ea[off + j + 3];
        a0 = fmaf(__int_as_float(e0.y), g_ht[(long long)e0.x * N_HID + c], a0);
        a1 = fmaf(__int_as_float(e1.y), g_ht[(long long)e1.x * N_HID + c], a1);
        a2 = fmaf(__int_as_float(e2.y), g_ht[(long long)e2.x * N_HID + c], a2);
        a3 = fmaf(__int_as_float(e3.y), g_ht[(long long)e3.x * N_HID + c], a3);
    }
    for (; j < cnt; j++) {
        int2 ee = g_ea[off + j];
        a0 = fmaf(__int_as_float(ee.y), g_ht[(long long)ee.x * N_HID + c], a0);
    }
    out[(long long)s * N_HID + c] = (a0 + a1) + (a2 + a3);
}

// ---------------------------------------------------------------------------
extern "C" void kernel_launch(void* const* d_in, const int* in_sizes, int n_in,
                              void* d_out, int out_size)
{
    const float* x   = (const float*)d_in[0];
    const void*  ei  = d_in[1];                 // [2, E] int32 or int64
    const float* Wfc = (const float*)d_in[2];
    const float* aw  = (const float*)d_in[3];
    const float* ab  = (const float*)d_in[4];

    float* out   = (float*)d_out;                   // [N, 64]
    float* alpha = (float*)d_out + N_NODES * N_HID; // [E]

    k_detect<<<1, 32>>>(ei);
    k_zero<<<(N_NODES + 255) / 256, 256>>>();
    k_gemm<<<(N_NODES + 31) / 32, 256>>>(x, Wfc, aw);
    k_score_hist<<<(N_EDGES + 255) / 256, 256>>>(ei, ab);
    k_scanA<<<SCAN_BLOCKS, 256>>>();
    k_scanB<<<1, 256>>>();
    k_scanC<<<SCAN_BLOCKS, 256>>>();
    k_place<<<(N_EDGES + 255) / 256, 256>>>(ei, alpha);
    k_accum<<<N_NODES / 4, 256>>>(out);
}